// round 2
// baseline (speedup 1.0000x reference)
#include <cuda_runtime.h>
#include <cstdint>

#define NQ 14
#define NL 6
#define DIM 16384                    // 2^14 amplitudes
#define NG (NL * NQ)                 // 84 rotation gates
#define NTHREADS 512
#define PAIRS (DIM / 2)              // 8192
#define PAIRS_PER_THREAD (PAIRS / NTHREADS)   // 16
#define AMPS_PER_THREAD (DIM / NTHREADS)      // 32
#define NWARPS (NTHREADS / 32)

// Per-gate GF(2)-frame data, computed on host (data-independent), passed by value.
struct GateTab {
    unsigned short mask[NG];    // stored-index XOR mask pairing the gate
    unsigned short row[NG];     // parity row: true-qubit bit = popc(idx & row) & 1
    unsigned char  pivot[NG];   // highest set bit of mask (pair enumeration pivot)
    unsigned short mrow0, mrow1; // measurement parity rows for qubits 0,1
};

// Rot gate 2x2 complex matrices, computed from device weights by prep kernel.
__device__ float2 g_gates[NG][4];   // [g][u00,u01,u10,u11]

__global__ void prep_gates_kernel(const float* __restrict__ w) {
    int g = blockIdx.x * blockDim.x + threadIdx.x;
    if (g >= NG) return;
    float phi   = w[g * 3 + 0];
    float theta = w[g * 3 + 1];
    float omega = w[g * 3 + 2];
    float st, ct;
    sincosf(theta * 0.5f, &st, &ct);
    float sp = 0.5f * (phi + omega);
    float sm = 0.5f * (phi - omega);
    float ssp, csp, ssm, csm;
    sincosf(sp, &ssp, &csp);
    sincosf(sm, &ssm, &csm);
    // Rot = RZ(omega) RY(theta) RZ(phi):
    // u00 = e^{-i(phi+omega)/2} ct ; u01 = -e^{+i(phi-omega)/2} st
    // u10 = e^{-i(phi-omega)/2} st ; u11 = e^{+i(phi+omega)/2} ct
    g_gates[g][0] = make_float2( csp * ct, -ssp * ct);
    g_gates[g][1] = make_float2(-csm * st, -ssm * st);
    g_gates[g][2] = make_float2( csm * st, -ssm * st);
    g_gates[g][3] = make_float2( csp * ct,  ssp * ct);
}

__global__ __launch_bounds__(NTHREADS, 1)
void sim_kernel(const float* __restrict__ x, float* __restrict__ out, GateTab tab) {
    extern __shared__ float2 s[];          // 16384 complex amplitudes = 128 KB
    __shared__ float ec[NQ], es[NQ];
    __shared__ float2 red[NWARPS];

    const int b   = blockIdx.x;
    const int tid = threadIdx.x;

    // --- encoding angles: RY(x*pi) -> factors cos(x*pi/2), sin(x*pi/2) ---
    if (tid < NQ) {
        float h = x[b * NQ + tid] * 1.5707963267948966f;
        float sv, cv;
        sincosf(h, &sv, &cv);
        ec[tid] = cv;
        es[tid] = sv;
    }
    __syncthreads();

    // --- init: encoded product state (real). idx bits: qubit q at bit (13-q). ---
    // idx = tid*32 + l : tid supplies qubits 0..8, l supplies qubits 9..13.
    float hi = 1.0f;
    #pragma unroll
    for (int q = 0; q < 9; q++)
        hi *= ((tid >> (8 - q)) & 1) ? es[q] : ec[q];
    #pragma unroll
    for (int l = 0; l < AMPS_PER_THREAD; l++) {
        float v = hi;
        #pragma unroll
        for (int q = 9; q < NQ; q++)
            v *= ((l >> (13 - q)) & 1) ? es[q] : ec[q];
        s[tid * AMPS_PER_THREAD + l] = make_float2(v, 0.0f);
    }
    __syncthreads();

    // --- 84 rotation gates; CNOTs are absorbed into masks/rows (GF(2) frame) ---
    for (int g = 0; g < NG; g++) {
        const float2 u00 = g_gates[g][0];
        const float2 u01 = g_gates[g][1];
        const float2 u10 = g_gates[g][2];
        const float2 u11 = g_gates[g][3];
        const unsigned m   = tab.mask[g];
        const unsigned r   = tab.row[g];
        const int      pv  = tab.pivot[g];
        const unsigned lowm = (1u << pv) - 1u;

        #pragma unroll
        for (int k = 0; k < PAIRS_PER_THREAD; k++) {
            unsigned p = (unsigned)(k * NTHREADS + tid);
            unsigned i = ((p & ~lowm) << 1) | (p & lowm);  // insert 0 at pivot bit
            unsigned j = i ^ m;                             // partner (pivot bit = 1)
            float2 A = s[i];
            float2 B = s[j];
            bool sw = (__popc(i & r) & 1) != 0;   // true-qubit bit of stored index i
            float2 a0 = sw ? B : A;
            float2 a1 = sw ? A : B;
            float2 n0, n1;
            n0.x = u00.x * a0.x - u00.y * a0.y + u01.x * a1.x - u01.y * a1.y;
            n0.y = u00.x * a0.y + u00.y * a0.x + u01.x * a1.y + u01.y * a1.x;
            n1.x = u10.x * a0.x - u10.y * a0.y + u11.x * a1.x - u11.y * a1.y;
            n1.y = u10.x * a0.y + u10.y * a0.x + u11.x * a1.y + u11.y * a1.x;
            s[i] = sw ? n1 : n0;
            s[j] = sw ? n0 : n1;
        }
        __syncthreads();
    }

    // --- measurement: <Z_0>, <Z_1> with parity rows in stored coordinates ---
    float z0 = 0.0f, z1 = 0.0f;
    #pragma unroll
    for (int l = 0; l < AMPS_PER_THREAD; l++) {
        unsigned idx = (unsigned)(tid * AMPS_PER_THREAD + l);
        float2 a = s[idx];
        float pr = a.x * a.x + a.y * a.y;
        z0 += (__popc(idx & tab.mrow0) & 1) ? -pr : pr;
        z1 += (__popc(idx & tab.mrow1) & 1) ? -pr : pr;
    }
    #pragma unroll
    for (int o = 16; o; o >>= 1) {
        z0 += __shfl_down_sync(0xffffffffu, z0, o);
        z1 += __shfl_down_sync(0xffffffffu, z1, o);
    }
    if ((tid & 31) == 0) red[tid >> 5] = make_float2(z0, z1);
    __syncthreads();
    if (tid == 0) {
        float a0 = 0.0f, a1 = 0.0f;
        #pragma unroll
        for (int w = 0; w < NWARPS; w++) { a0 += red[w].x; a1 += red[w].y; }
        out[b * 2 + 0] = a0;
        out[b * 2 + 1] = a1;
    }
}

extern "C" void kernel_launch(void* const* d_in, const int* in_sizes, int n_in,
                              void* d_out, int out_size) {
    const float* x = (const float*)d_in[0];       // (B, 14)
    const float* w = (const float*)d_in[1];       // (6, 14, 3)
    float* out = (float*)d_out;                   // (B, 2)
    const int B = in_sizes[0] / NQ;

    // Build GF(2) frame tables on host (fixed circuit structure, data-independent).
    // T: stored -> true index map. R[q] = row q of T (parity mask).
    // Minv[q] = column q of T^{-1} (pair mask). Qubit q lives at bit (13-q).
    GateTab tab;
    unsigned short R[NQ], Minv[NQ];
    for (int q = 0; q < NQ; q++)
        R[q] = Minv[q] = (unsigned short)(1u << (13 - q));
    int g = 0;
    for (int l = 0; l < NL; l++) {
        for (int q = 0; q < NQ; q++) {
            tab.mask[g] = Minv[q];
            tab.row[g]  = R[q];
            int pv = 0;
            unsigned mm = Minv[q];
            while (mm >> (pv + 1)) pv++;          // highest set bit
            tab.pivot[g] = (unsigned char)pv;
            g++;
        }
        int r = (l % (NQ - 1)) + 1;               // PennyLane default ranges
        for (int q = 0; q < NQ; q++) {
            int c = q, t = (q + r) % NQ;
            R[t]    ^= R[c];                       // T <- CNOT(c,t) o T  (row op)
            Minv[c] ^= Minv[t];                    // T^-1 <- T^-1 o CNOT (col op)
        }
    }
    tab.mrow0 = R[0];
    tab.mrow1 = R[1];

    cudaFuncSetAttribute(sim_kernel, cudaFuncAttributeMaxDynamicSharedMemorySize,
                         DIM * (int)sizeof(float2));

    prep_gates_kernel<<<1, 128>>>(w);
    sim_kernel<<<B, NTHREADS, DIM * sizeof(float2)>>>(x, out, tab);
}

// round 3
// speedup vs baseline: 1.5990x; 1.5990x over previous
#include <cuda_runtime.h>
#include <cstdint>

#define NQ 14
#define NL 6
#define DIM 16384
#define NG (NL * NQ)                 // 84 rotation gates
#define NTHREADS 512
#define AMPS_PER_THREAD (DIM / NTHREADS)      // 32
#define NWARPS (NTHREADS / 32)
#define NGROUPS (NL * 3)             // 3 fused groups per layer (5,5,4)

// One fused gate-group: K gates (5 or 4) with commuting targets.
struct Group {
    unsigned short loc2glob[32];  // local coset index -> XOR offset (XOR of masks)
    unsigned short row[5];        // parity rows (true-qubit bit of an index)
    unsigned char  npos[10];      // non-pivot bit positions (coset-rep expansion)
    unsigned char  gbase;         // first gate index into g_gates
};
struct Tab2 {
    Group grp[NGROUPS];
    unsigned short mrow0, mrow1;  // measurement parity rows
};

// Rot gate 2x2 complex matrices, computed from device weights by prep kernel.
__device__ float2 g_gates[NG][4];   // [g][u00,u01,u10,u11]

__global__ void prep_gates_kernel(const float* __restrict__ w) {
    int g = blockIdx.x * blockDim.x + threadIdx.x;
    if (g >= NG) return;
    float phi   = w[g * 3 + 0];
    float theta = w[g * 3 + 1];
    float omega = w[g * 3 + 2];
    float st, ct;
    sincosf(theta * 0.5f, &st, &ct);
    float ssp, csp, ssm, csm;
    sincosf(0.5f * (phi + omega), &ssp, &csp);
    sincosf(0.5f * (phi - omega), &ssm, &csm);
    // Rot = RZ(omega) RY(theta) RZ(phi)
    g_gates[g][0] = make_float2( csp * ct, -ssp * ct);
    g_gates[g][1] = make_float2(-csm * st, -ssm * st);
    g_gates[g][2] = make_float2( csm * st, -ssm * st);
    g_gates[g][3] = make_float2( csp * ct,  ssp * ct);
}

template<int KG>
__device__ __forceinline__ void do_group(float2* __restrict__ s,
                                         const Group& grp, int tid) {
    const int NCOS = (DIM >> KG) / NTHREADS;     // 1 for KG=5, 2 for KG=4
    const float2* __restrict__ gm = &g_gates[grp.gbase][0];
    #pragma unroll
    for (int ci = 0; ci < NCOS; ci++) {
        unsigned c = (unsigned)tid + (unsigned)ci * NTHREADS;
        unsigned base = 0;
        #pragma unroll
        for (int b = 0; b < 14 - KG; b++)
            base |= ((c >> b) & 1u) << grp.npos[b];

        float2 a[1 << KG];
        #pragma unroll
        for (int t = 0; t < (1 << KG); t++)
            a[t] = s[base ^ grp.loc2glob[t]];

        #pragma unroll
        for (int j = 0; j < KG; j++) {
            float2 u00 = gm[j * 4 + 0], u01 = gm[j * 4 + 1];
            float2 u10 = gm[j * 4 + 2], u11 = gm[j * 4 + 3];
            // true-qubit bit of local element = parity(base&row) ^ localbit_j
            bool swb = (__popc(base & (unsigned)grp.row[j]) & 1) != 0;
            float2 v00 = swb ? u11 : u00;
            float2 v01 = swb ? u10 : u01;
            float2 v10 = swb ? u01 : u10;
            float2 v11 = swb ? u00 : u11;
            #pragma unroll
            for (int t = 0; t < (1 << KG); t++) {
                if (t & (1 << j)) continue;
                const int t2 = t | (1 << j);
                float2 p = a[t], q = a[t2];
                float2 n0, n1;
                n0.x = v00.x * p.x - v00.y * p.y + v01.x * q.x - v01.y * q.y;
                n0.y = v00.x * p.y + v00.y * p.x + v01.x * q.y + v01.y * q.x;
                n1.x = v10.x * p.x - v10.y * p.y + v11.x * q.x - v11.y * q.y;
                n1.y = v10.x * p.y + v10.y * p.x + v11.x * q.y + v11.y * q.x;
                a[t]  = n0;
                a[t2] = n1;
            }
        }
        #pragma unroll
        for (int t = 0; t < (1 << KG); t++)
            s[base ^ grp.loc2glob[t]] = a[t];
    }
}

__global__ __launch_bounds__(NTHREADS, 1)
void sim_kernel(const float* __restrict__ x, float* __restrict__ out, Tab2 tab) {
    extern __shared__ float2 s[];          // 16384 complex amplitudes = 128 KB
    __shared__ float ec[NQ], es[NQ];
    __shared__ float2 red[NWARPS];

    const int b   = blockIdx.x;
    const int tid = threadIdx.x;

    if (tid < NQ) {
        float h = x[b * NQ + tid] * 1.5707963267948966f;
        float sv, cv;
        sincosf(h, &sv, &cv);
        ec[tid] = cv;
        es[tid] = sv;
    }
    __syncthreads();

    // init: encoded real product state; qubit q at bit (13-q)
    float hi = 1.0f;
    #pragma unroll
    for (int q = 0; q < 9; q++)
        hi *= ((tid >> (8 - q)) & 1) ? es[q] : ec[q];
    #pragma unroll
    for (int l = 0; l < AMPS_PER_THREAD; l++) {
        float v = hi;
        #pragma unroll
        for (int q = 9; q < NQ; q++)
            v *= ((l >> (13 - q)) & 1) ? es[q] : ec[q];
        s[tid * AMPS_PER_THREAD + l] = make_float2(v, 0.0f);
    }
    __syncthreads();

    // 18 fused passes: per layer, groups of (5,5,4) commuting gates
    #pragma unroll 1
    for (int l = 0; l < NL; l++) {
        do_group<5>(s, tab.grp[l * 3 + 0], tid); __syncthreads();
        do_group<5>(s, tab.grp[l * 3 + 1], tid); __syncthreads();
        do_group<4>(s, tab.grp[l * 3 + 2], tid); __syncthreads();
    }

    // measurement: <Z_0>, <Z_1> via parity rows in stored coordinates
    float z0 = 0.0f, z1 = 0.0f;
    #pragma unroll
    for (int l = 0; l < AMPS_PER_THREAD; l++) {
        unsigned idx = (unsigned)(tid * AMPS_PER_THREAD + l);
        float2 a = s[idx];
        float pr = a.x * a.x + a.y * a.y;
        z0 += (__popc(idx & tab.mrow0) & 1) ? -pr : pr;
        z1 += (__popc(idx & tab.mrow1) & 1) ? -pr : pr;
    }
    #pragma unroll
    for (int o = 16; o; o >>= 1) {
        z0 += __shfl_down_sync(0xffffffffu, z0, o);
        z1 += __shfl_down_sync(0xffffffffu, z1, o);
    }
    if ((tid & 31) == 0) red[tid >> 5] = make_float2(z0, z1);
    __syncthreads();
    if (tid == 0) {
        float a0 = 0.0f, a1 = 0.0f;
        #pragma unroll
        for (int w = 0; w < NWARPS; w++) { a0 += red[w].x; a1 += red[w].y; }
        out[b * 2 + 0] = a0;
        out[b * 2 + 1] = a1;
    }
}

extern "C" void kernel_launch(void* const* d_in, const int* in_sizes, int n_in,
                              void* d_out, int out_size) {
    const float* x = (const float*)d_in[0];       // (B, 14)
    const float* w = (const float*)d_in[1];       // (6, 14, 3)
    float* out = (float*)d_out;                   // (B, 2)
    const int B = in_sizes[0] / NQ;

    // --- host: GF(2) frame tracking + per-group echelon tables ---
    Tab2 tab;
    unsigned short R[NQ], Minv[NQ];
    for (int q = 0; q < NQ; q++)
        R[q] = Minv[q] = (unsigned short)(1u << (13 - q));

    for (int l = 0; l < NL; l++) {
        int offs[4] = {0, 5, 10, 14};             // groups of 5,5,4
        for (int gi = 0; gi < 3; gi++) {
            Group& G = tab.grp[l * 3 + gi];
            int off = offs[gi], kg = offs[gi + 1] - offs[gi];
            unsigned short m[5], r[5];
            for (int i = 0; i < kg; i++) {
                m[i] = Minv[off + i];
                r[i] = R[off + i];
                G.row[i] = r[i];
            }
            for (int i = kg; i < 5; i++) G.row[i] = 0;
            G.gbase = (unsigned char)(l * NQ + off);
            // echelonize to find pivot bits (highest-bit pivots)
            unsigned red_[5]; int piv[5];
            for (int i = 0; i < kg; i++) {
                unsigned v = m[i];
                for (int j = 0; j < i; j++)
                    if ((v >> piv[j]) & 1u) v ^= red_[j];
                int p = 31 - __builtin_clz(v);    // masks are linearly independent
                piv[i] = p; red_[i] = v;
            }
            bool ispiv[14] = {};
            for (int i = 0; i < kg; i++) ispiv[piv[i]] = true;
            int idx = 0;
            for (int bpos = 0; bpos < 14; bpos++)
                if (!ispiv[bpos]) G.npos[idx++] = (unsigned char)bpos;
            while (idx < 10) G.npos[idx++] = 0;
            // local->global XOR offsets from ORIGINAL masks
            for (int t = 0; t < 32; t++) {
                unsigned xr = 0;
                for (int i = 0; i < kg; i++)
                    if ((t >> i) & 1) xr ^= m[i];
                G.loc2glob[t] = (unsigned short)(t < (1 << kg) ? xr : 0);
            }
        }
        // layer's CNOT ring updates the frame (entering next layer)
        int r = (l % (NQ - 1)) + 1;
        for (int q = 0; q < NQ; q++) {
            int c = q, t = (q + r) % NQ;
            R[t]    ^= R[c];
            Minv[c] ^= Minv[t];
        }
    }
    tab.mrow0 = R[0];
    tab.mrow1 = R[1];

    cudaFuncSetAttribute(sim_kernel, cudaFuncAttributeMaxDynamicSharedMemorySize,
                         DIM * (int)sizeof(float2));

    prep_gates_kernel<<<1, 128>>>(w);
    sim_kernel<<<B, NTHREADS, DIM * sizeof(float2)>>>(x, out, tab);
}